// round 15
// baseline (speedup 1.0000x reference)
#include <cuda_runtime.h>
#include <math.h>

// ---------------- problem constants ----------------
#define BB   8
#define CC   684
#define HHD  16
#define WWD  64
#define PP   1024
#define TT   32
#define HID  256
#define ATT  512
#define COVD 512
#define VOC  111
#define LOCD 432
#define KC   11
#define RAT  16

typedef unsigned long long ull;

// ---------------- scratch ----------------
__device__ float d_mask[BB*PP];
__device__ float d_msum[BB];
__device__ float d_avg[BB*CC];
__device__ float d_hid0[BB*HID];
__device__ float d_locw[BB*HID];
__device__ float d_kcovT[KC*KC*COVD];
__device__ float d_KfT[(KC*KC+3)*ATT];    // +3 pad rows for prefetch pipeline
__device__ float d_ctrans[(size_t)BB*PP*ATT];
__device__ float d_embseq[TT*BB*HID];
__device__ float d_giall[TT*BB*3*HID];
__device__ float d_embwall[TT*BB*HID];
__device__ float d_queryall[TT*BB*ATT];
__device__ float d_stall[TT*BB*HID];
__device__ float d_asum[2][BB*PP];
__device__ float d_ealpha[2][BB*PP];      // exp(e - Mrow) * mask
__device__ float d_MS[2][BB*32];          // per (b,row): (max, expsum)
__device__ float d_Whh2[HID*3*HID];       // [c/2][row768][2]
__device__ float d_Whq2[HID*ATT];         // [c/2][q512][2]
__device__ float d_Wst2[HID*HID];         // [c/2][j256][2]
__device__ float d_Wct2[(CC/2)*2*HID];    // [c/2][j256][2]
__device__ float d_WoutT[HID*VOC];        // [c][v]
__device__ unsigned d_bcnt[BB*32];        // loop barrier, padded
__device__ unsigned d_qflag[BB*32];       // chain progress flag, padded

// ---------------- helpers ----------------
__device__ __forceinline__ float warp_red(float s){
#pragma unroll
    for(int o=16;o;o>>=1) s += __shfl_down_sync(0xffffffffu, s, o);
    return s;
}
__device__ __forceinline__ ull pack2(float lo, float hi){
    ull r; asm("mov.b64 %0, {%1,%2};" : "=l"(r) : "f"(lo), "f"(hi)); return r;
}
__device__ __forceinline__ void fma2(ull &d, ull a, ull b){
    asm("fma.rn.f32x2 %0, %1, %2, %0;" : "+l"(d) : "l"(a), "l"(b));
}
__device__ __forceinline__ float2 unpack2(ull v){
    float2 f; asm("mov.b64 {%0,%1}, %2;" : "=f"(f.x), "=f"(f.y) : "l"(v)); return f;
}
__device__ __forceinline__ float tanha(float x){
    asm("tanh.approx.f32 %0, %0;" : "+f"(x)); return x;
}

// =================== Launch 0: k_preA ===================
#define PA_KC   8
#define PA_EMB  (PA_KC+242)
#define PA_WHH  (PA_EMB+256)
#define PA_WHQ  (PA_WHH+768)
#define PA_WST  (PA_WHQ+512)
#define PA_WOUT (PA_WST+256)
#define PA_WCT  (PA_WOUT+112)
#define PA_TOT  (PA_WCT+684)

__global__ void __launch_bounds__(256) k_preA(
    const float* __restrict__ imask, const float* __restrict__ K_cov,
    const int*   __restrict__ labels,const float* __restrict__ emb,
    const float* __restrict__ W_hh,  const float* __restrict__ W_hq,
    const float* __restrict__ W_state,const float* __restrict__ W_out,
    const float* __restrict__ W_ctx)
{
    const int blk = blockIdx.x, tid = threadIdx.x;
    __shared__ float red[256];

    if(blk < PA_KC){
        int b = blk;
        float s = 0.f;
        for(int i=tid;i<PP;i+=256){
            int hh = i>>6, ww = i&63;
            float m = imask[(size_t)b*(256*1024) + (size_t)(hh*RAT)*1024 + ww*RAT];
            d_mask[b*PP+i] = m;
            d_asum[0][b*PP+i] = 0.f;
            s += m;
        }
        red[tid]=s; __syncthreads();
        for(int o=128;o;o>>=1){ if(tid<o) red[tid]+=red[tid+o]; __syncthreads(); }
        if(tid==0){ d_msum[b]=red[0]; d_bcnt[b*32]=0u; d_qflag[b*32]=0u; }
    } else if(blk < PA_EMB){
        int e = (blk-PA_KC)*256 + tid;
        if(e < COVD*KC*KC){
            int c = e/(KC*KC), ij = e - c*(KC*KC);
            d_kcovT[ij*COVD + c] = K_cov[e];
        }
    } else if(blk < PA_WHH){
        int e = (blk-PA_EMB)*256 + tid;
        int k = e & (HID-1);
        int tb = e >> 8;
        int b = tb & 7, t = tb >> 3;
        int lbl = (t==0) ? 1 : labels[b*TT + (t-1)];
        d_embseq[e] = emb[(size_t)lbl*HID + k];
    } else if(blk < PA_WHQ){
        int e = (blk-PA_WHH)*256 + tid;   // 768*256
        int r = e >> 8, c = e & 255;
        d_Whh2[(c>>1)*1536 + r*2 + (c&1)] = W_hh[e];
    } else if(blk < PA_WST){
        int e = (blk-PA_WHQ)*256 + tid;   // 512*256
        int q = e >> 8, c = e & 255;
        d_Whq2[(c>>1)*1024 + q*2 + (c&1)] = W_hq[e];
    } else if(blk < PA_WOUT){
        int e = (blk-PA_WST)*256 + tid;   // 256*256
        int j = e >> 8, c = e & 255;
        d_Wst2[(c>>1)*512 + j*2 + (c&1)] = W_state[e];
    } else if(blk < PA_WCT){
        int e = (blk-PA_WOUT)*256 + tid;  // VOC*256
        if(e < VOC*HID){
            int v = e >> 8, c = e & 255;
            d_WoutT[c*VOC + v] = W_out[e];
        }
    } else {
        int e = (blk-PA_WCT)*256 + tid;   // 256*684 = 175104
        if(e < HID*CC){
            int c = e % CC, j = e / CC;
            d_Wct2[(c>>1)*512 + j*2 + (c&1)] = W_ctx[(size_t)j*CC + c];
        }
    }
}

// =================== Launch 1: k_preB (GEMMs) ===================
#define PB_GI  256
#define PB_EW  (PB_GI+48)
#define PB_KF  (PB_EW+16)
#define PB_AVG (PB_KF+16)
#define PB_TOT (PB_AVG+684)

__device__ void gemm128cnn(const float* __restrict__ cnn,
                           const float* __restrict__ Wt,
                           const float* __restrict__ bias,
                           float* __restrict__ out, int px, int nx,
                           float2 (*As2)[137], float (*Bs)[138])
{
    int p0 = px*128, a0 = nx*128;
    int bb = px >> 3, pp0 = (px & 7) * 128;
    int tid = threadIdx.x;
    int tx = tid & 15, ty = tid >> 4;
    ull acc[8][4];
#pragma unroll
    for(int r=0;r<8;r++)
#pragma unroll
        for(int aa=0;aa<4;aa++) acc[r][aa]=0ull;

    for(int ck=0; ck<CC; ck+=12){
#pragma unroll
        for(int l=0;l<6;l++){
            int lin = tid + l*256;
            int r = lin & 127, k = lin >> 7;
            float av = cnn[((size_t)(bb*CC + ck + k))*PP + pp0 + r];
            As2[k][r] = make_float2(av, av);
        }
#pragma unroll
        for(int l=0;l<6;l++){
            int lin = tid + l*256;
            int k = lin % 12, r = lin / 12;
            Bs[k][r] = Wt[(size_t)(a0+r)*CC + ck + k];
        }
        __syncthreads();
#pragma unroll
        for(int k=0;k<12;k++){
            ull ra[8], rb[4];
#pragma unroll
            for(int r=0;r<8;r++) ra[r] = *(const ull*)&As2[k][ty*8+r];
#pragma unroll
            for(int aa=0;aa<4;aa++) rb[aa] = *(const ull*)&Bs[k][tx*2 + aa*32];
#pragma unroll
            for(int r=0;r<8;r++)
#pragma unroll
                for(int aa=0;aa<4;aa++) fma2(acc[r][aa], ra[r], rb[aa]);
        }
        __syncthreads();
    }
#pragma unroll
    for(int r=0;r<8;r++){
        int p = p0 + ty*8 + r;
#pragma unroll
        for(int aa=0;aa<4;aa++){
            int a = a0 + tx*2 + aa*32;
            float2 v = unpack2(acc[r][aa]);
            out[(size_t)p*ATT + a]   = v.x + bias[a];
            out[(size_t)p*ATT + a+1] = v.y + bias[a+1];
        }
    }
}

__device__ void gemm64(const float* __restrict__ A, int M, int K,
                       const float* __restrict__ Wt, const float* __restrict__ bias,
                       float* __restrict__ out, int N, int ptile, int ntile,
                       float2 (*As)[68], float (*Bs)[68])
{
    int pt = ptile*64, at = ntile*64;
    int tid = threadIdx.x;
    int tx = tid & 15, ty = tid >> 4;
    ull acc2[4][2];
#pragma unroll
    for(int i=0;i<4;i++){ acc2[i][0]=0ull; acc2[i][1]=0ull; }

    for(int c0=0;c0<K;c0+=16){
#pragma unroll
        for(int l=0;l<4;l++){
            int lin = tid + l*256;
            int k = lin & 15, r = lin >> 4;
            int c = c0 + k;
            float av = (c < K && pt+r < M) ? A[((size_t)(pt+r))*K + c] : 0.f;
            As[k][r] = make_float2(av, av);
            Bs[k][r] = (c < K) ? Wt[((size_t)(at+r))*K + c] : 0.f;
        }
        __syncthreads();
#pragma unroll
        for(int k=0;k<16;k++){
            ull ra2[4], rb2[2];
#pragma unroll
            for(int i=0;i<4;i++) ra2[i] = *(const ull*)&As[k][ty*4+i];
            rb2[0] = *(const ull*)&Bs[k][tx*4];
            rb2[1] = *(const ull*)&Bs[k][tx*4+2];
#pragma unroll
            for(int i=0;i<4;i++){
                fma2(acc2[i][0], ra2[i], rb2[0]);
                fma2(acc2[i][1], ra2[i], rb2[1]);
            }
        }
        __syncthreads();
    }
#pragma unroll
    for(int i=0;i<4;i++){
        int p = pt + ty*4 + i;
        if(p < M){
#pragma unroll
            for(int jp=0;jp<2;jp++){
                int aa = at + tx*4 + jp*2;
                float2 v = unpack2(acc2[i][jp]);
                float b0 = bias ? bias[aa]   : 0.f;
                float b1 = bias ? bias[aa+1] : 0.f;
                out[(size_t)p*N + aa]   = v.x + b0;
                out[(size_t)p*N + aa+1] = v.y + b1;
            }
        }
    }
}

__global__ void __launch_bounds__(256,2) k_preB(
    const float* __restrict__ cnn,
    const float* __restrict__ K_enc, const float* __restrict__ b_enc,
    const float* __restrict__ W_ih,  const float* __restrict__ b_ih,
    const float* __restrict__ W_embw,const float* __restrict__ b_embw,
    const float* __restrict__ W_att)
{
    __shared__ float2 As2[12][137];
    __shared__ float  Bsb[12][138];
    __shared__ float2 As[16][68];
    __shared__ float  Bs[16][68];
    const int blk = blockIdx.x;

    if(blk < PB_GI){
        int i = blk;
        gemm128cnn(cnn, K_enc, b_enc, d_ctrans, i & 63, i >> 6, As2, Bsb);
    } else if(blk < PB_EW){
        int i = blk - PB_GI;
        gemm64(d_embseq, TT*BB, HID, W_ih, b_ih, d_giall, 3*HID, i & 3, i >> 2, As, Bs);
    } else if(blk < PB_KF){
        int i = blk - PB_EW;
        gemm64(d_embseq, TT*BB, HID, W_embw, b_embw, d_embwall, HID, i & 3, i >> 2, As, Bs);
    } else if(blk < PB_AVG){
        int i = blk - PB_KF;
        gemm64(d_kcovT, KC*KC, COVD, W_att, (const float*)0, d_KfT, ATT, i & 1, i >> 1, As, Bs);
    } else {
        int gw = (blk - PB_AVG)*8 + (threadIdx.x >> 5);
        int lane = threadIdx.x & 31;
        if(gw < BB*CC){
            int b = gw / CC;
            const float* x = cnn + (size_t)gw*PP;
            const float* m = d_mask + b*PP;
            float s = 0.f;
            for(int p=lane;p<PP;p+=32) s += x[p]*m[p];
            s = warp_red(s);
            if(lane==0) d_avg[gw] = s / d_msum[b];
        }
    }
}

// =================== Launch 2: k_preC ===================
__global__ void __launch_bounds__(256) k_preC(
    const float* __restrict__ W_init, const float* __restrict__ b_init,
    const float* __restrict__ W_loc,  const float* __restrict__ b_loc,
    const float* __restrict__ locp)
{
    int gw = blockIdx.x*8 + (threadIdx.x >> 5);
    int lane = threadIdx.x & 31;
    if(gw < BB*HID){
        int b = gw / HID, j = gw - b*HID;
        const float* wv = W_init + (size_t)j*CC;
        const float* av = d_avg + b*CC;
        float s = 0.f;
        for(int c=lane;c<CC;c+=32) s += wv[c]*av[c];
        s = warp_red(s);
        if(lane==0) d_hid0[gw] = tanhf(s + b_init[j]);
    } else if(gw < 2*BB*HID){
        int g2 = gw - BB*HID;
        int b = g2 / HID, j = g2 - b*HID;
        const float* wv = W_loc + (size_t)j*LOCD;
        const float* xv = locp + (size_t)b*LOCD;
        float s = 0.f;
        for(int c=lane;c<LOCD;c+=32) s += wv[c]*xv[c];
        s = warp_red(s);
        if(lane==0) d_locw[g2] = s + b_loc[j];
    }
}

// =================== Launch 3: k_loop (persistent; 1024 threads, 64 regs) ===================
__global__ void __launch_bounds__(1024,1) k_loop(
    const float* __restrict__ cnn,
    const float* __restrict__ Wac,   const float* __restrict__ bac,
    const float* __restrict__ bout,
    const float* __restrict__ bhh,   const float* __restrict__ bhq,
    const float* __restrict__ bstate,const float* __restrict__ bctx,
    float* __restrict__ out_probs,   float* __restrict__ out_alphas)
{
    const int bid = blockIdx.x;       // 0..143
    const int b = bid / 18;
    const int h = bid - b*18;         // 0..15 E rows; 16 = P block; 17 = chain producer
    const int tid = threadIdx.x;
    const int lane = tid & 31, wid = tid >> 5;
    unsigned bt = 0;

    __shared__ float2 taps2[KC*74];
    __shared__ float  spart[8][4][8];
    __shared__ float  wred[4];
    __shared__ float  rs_s[16];
    __shared__ int    wcnt[32];
    __shared__ int    pl[64];
    __shared__ float  wl[64];
    __shared__ int    nact_s;
    __shared__ float  sacc[4][HID];
    __shared__ float  os[HID];
    __shared__ float  pp8[8][128];
    __shared__ __align__(8) float hc[HID];
    __shared__ __align__(8) float gv[3*HID];   // chain gates; reused as cx[684] in P

    const float bac0 = bac[0];

    // ================= chain producer block =================
    if(h == 17){
        if(tid < HID) hc[tid] = d_hid0[b*HID + tid];
        __syncthreads();
        for(int t=0; t<TT; t++){
            const ull* h2 = (const ull*)hc;
            if(tid < 3*HID){
                int row = tid;
                ull acc = 0ull;
                const ull* wp = (const ull*)d_Whh2;
#pragma unroll 16
                for(int c2=0;c2<128;c2++)
                    fma2(acc, wp[c2*768 + row], h2[c2]);
                float2 v = unpack2(acc);
                gv[row] = v.x + v.y;
            }
            __syncthreads();
            if(tid < HID){
                int j = tid;
                float hr = bhh[j]       + gv[j];
                float hz = bhh[HID+j]   + gv[HID+j];
                float hv = bhh[2*HID+j] + gv[2*HID+j];
                const float* gi = d_giall + (size_t)(t*BB+b)*3*HID;
                float r = 1.f/(1.f+expf(-(gi[j]+hr)));
                float z = 1.f/(1.f+expf(-(gi[HID+j]+hz)));
                float n = tanhf(gi[2*HID+j] + r*hv);
                gv[j] = (1.f - z)*n + z*hc[j];
            }
            __syncthreads();
            if(tid < HID) hc[tid] = gv[tid];
            __syncthreads();
            const ull* hn2 = (const ull*)hc;
            if(tid < ATT){
                int q = tid;
                ull aq = 0ull;
                const ull* wq = (const ull*)d_Whq2;
#pragma unroll 16
                for(int c2=0;c2<128;c2++)
                    fma2(aq, wq[c2*512 + q], hn2[c2]);
                float2 vq = unpack2(aq);
                d_queryall[(size_t)(t*BB+b)*ATT + q] = bhq[q] + vq.x + vq.y;
            } else if(tid < ATT + HID){
                int j = tid - ATT;
                ull as2 = 0ull;
                const ull* ws = (const ull*)d_Wst2;
#pragma unroll 16
                for(int c2=0;c2<128;c2++)
                    fma2(as2, ws[c2*256 + j], hn2[c2]);
                float2 vs = unpack2(as2);
                d_stall[(size_t)(t*BB+b)*HID + j] = bstate[j] + bctx[j]
                    + d_embwall[(size_t)(t*BB+b)*HID + j] + vs.x + vs.y;
            }
            __threadfence();
            __syncthreads();
            if(tid==0) *((volatile unsigned*)&d_qflag[b*32]) = (unsigned)(t+1);
        }
        return;
    }

    // ================= E / P blocks =================
    for(int p=0; p<=TT; p++){
        float M = -3.4e38f, S1e = 1e-10f;
        const float* ms = d_MS[(p-1)&1] + b*32;
        if(p > 0){
            float s = 0.f;
#pragma unroll
            for(int r=0;r<16;r++) M = fmaxf(M, ms[2*r]);
#pragma unroll
            for(int r=0;r<16;r++) s += expf(ms[2*r]-M)*ms[2*r+1];
            S1e = s + 1e-10f;
        }

        if(h < 16){
            if(p > 0){
                if(tid < 16) rs_s[tid] = expf(ms[2*tid]-M)/S1e;
                __syncthreads();
                if(tid < 64){
                    int px = b*PP + h*WWD + tid;
                    float a = d_ealpha[(p-1)&1][px] * rs_s[h];
                    out_alphas[((size_t)(b*TT + (p-1)))*PP + h*WWD + tid] = a;
                    d_asum[p&1][px] = d_asum[(p-1)&1][px] + a;
                }
                if(p < TT){
                    if(tid < KC*74){
                        int idx = tid;
                        int i = idx/74, w2 = idx - i*74;
                        int r = h + i - 5, wg = w2 - 5;
                        float v = 0.f;
                        if(r>=0 && r<HHD && wg>=0 && wg<WWD){
                            int px = b*PP + r*WWD + wg;
                            v = d_asum[(p-1)&1][px] + d_ealpha[(p-1)&1][px]*rs_s[r];
                        }
                        taps2[idx] = make_float2(v, v);
                    }
                    // merged: taps visibility + query(p) availability
                    if(tid==0){
                        while(*((volatile unsigned*)&d_qflag[b*32]) < (unsigned)(p+1))
                            __nanosleep(32);
                    }
                    __syncthreads();
                }
            }

            if(p < TT){
                const int ag = tid & 127, wg = tid >> 7;   // 8 w-groups
                const int a0 = ag << 2,  w0 = wg << 3;     // 8 w per thread

                if(p == 0){
                    if(tid==0){
                        while(*((volatile unsigned*)&d_qflag[b*32]) < (unsigned)(p+1))
                            __nanosleep(32);
                    }
                    __syncthreads();
                }

                ull a01[8], a23[8];
#pragma unroll
                for(int w=0;w<8;w++){ a01[w]=0ull; a23[w]=0ull; }

                if(p > 0){
                    // rolling depth-2 kf prefetch; static taps offsets
                    const float* kfp = d_KfT + a0;
                    float4 pre0 = *(const float4*)(kfp);
                    float4 pre1 = *(const float4*)(kfp + ATT);
                    const float* kfn = kfp + (size_t)2*ATT;
#pragma unroll 1
                    for(int i=0;i<KC;i++){
                        const ull* trow = (const ull*)(&taps2[i*74 + w0]);
#pragma unroll
                        for(int j=0;j<KC;j++){
                            ull k01 = pack2(pre0.x, pre0.y);
                            ull k23 = pack2(pre0.z, pre0.w);
                            pre0 = pre1;
                            pre1 = *(const float4*)kfn;    // pad rows keep in-bounds
                            kfn += ATT;
#pragma unroll
                            for(int w=0;w<8;w++){
                                ull tp = trow[j+w];
                                fma2(a01[w], k01, tp);
                                fma2(a23[w], k23, tp);
                            }
                        }
                    }
                }

                // epilogue
                float4 q4  = *(const float4*)(d_queryall + (size_t)(p*BB+b)*ATT + a0);
                float4 wa4 = *(const float4*)(Wac + a0);
                const float* ctbase = d_ctrans + ((size_t)(b*PP + h*WWD + w0))*ATT + a0;
                int wiw = (tid >> 5) & 3;   // warp within wg (4 warps per wg)
#pragma unroll
                for(int w=0;w<8;w++){
                    float4 ct = *(const float4*)(ctbase + (size_t)w*ATT);
                    float2 v01 = unpack2(a01[w]);
                    float2 v23 = unpack2(a23[w]);
                    float v = wa4.x * tanha(q4.x + v01.x + ct.x)
                            + wa4.y * tanha(q4.y + v01.y + ct.y)
                            + wa4.z * tanha(q4.z + v23.x + ct.z)
                            + wa4.w * tanha(q4.w + v23.y + ct.w);
#pragma unroll
                    for(int o=16;o;o>>=1) v += __shfl_down_sync(0xffffffffu, v, o);
                    if(lane==0) spart[wg][wiw][w] = v;
                }
                __syncthreads();
                float ev = 0.f;
                if(tid < 64){
                    int wgo = tid >> 3, wlx = tid & 7;
                    ev = spart[wgo][0][wlx] + spart[wgo][1][wlx]
                       + spart[wgo][2][wlx] + spart[wgo][3][wlx] + bac0;
                    float m = ev;
#pragma unroll
                    for(int o=16;o;o>>=1) m = fmaxf(m, __shfl_xor_sync(0xffffffffu, m, o));
                    if(lane==0) wred[wid] = m;
                }
                __syncthreads();
                float Mr = fmaxf(wred[0], wred[1]);
                if(tid < 64){
                    int px = b*PP + h*WWD + tid;
                    float s = expf(ev - Mr)*d_mask[px];
                    d_ealpha[p&1][px] = s;
#pragma unroll
                    for(int o=16;o;o>>=1) s += __shfl_xor_sync(0xffffffffu, s, o);
                    if(lane==0) wred[2+wid] = s;
                }
                __syncthreads();
                if(tid==0){
                    float* msd = d_MS[p&1] + b*32 + h*2;
                    msd[0] = Mr; msd[1] = wred[2] + wred[3];
                }
            }
        } else {
            // ================= P block: ctx + probs for t' = p-1 =================
            if(p > 0){
                int t2 = p-1;
                if(tid < 16) rs_s[tid] = expf(ms[2*tid]-M)/S1e;
                if(tid==0){
                    while(*((volatile unsigned*)&d_qflag[b*32]) < (unsigned)p)
                        __nanosleep(32);
                }
                __syncthreads();

                float a0 = d_ealpha[(p-1)&1][b*PP + tid] * rs_s[tid>>6];

                bool act = a0 > 0.02f;
                unsigned m0 = __ballot_sync(0xffffffffu, act);
                if(lane==0) wcnt[wid] = __popc(m0);
                __syncthreads();
                if(tid < 32){
                    int v = wcnt[tid], sc = v;
#pragma unroll
                    for(int o=1;o<32;o<<=1){ int u=__shfl_up_sync(0xffffffffu, sc, o); if(tid>=o) sc += u; }
                    wcnt[tid] = sc - v;
                    if(tid==31) nact_s = sc;
                }
                __syncthreads();
                int base = wcnt[wid];
                unsigned lm = (1u<<lane) - 1u;
                if(act){ int idx = base + __popc(m0 & lm); if(idx<64){ pl[idx]=tid; wl[idx]=a0; } }
                __syncthreads();

                // ---- C-space ctx gather from cnn directly (reuse gv as cx) ----
                float* cx = gv;
                if(tid < CC){
                    int n = nact_s < 64 ? nact_s : 64;
                    const float* cp = cnn + ((size_t)(b*CC + tid))*PP;
                    float s = 0.f;
                    for(int i=0;i<n;i++)
                        s = fmaf(wl[i], cp[pl[i]], s);
                    cx[tid] = s;
                }
                __syncthreads();
                // ---- ctx @ W_ctx^T via packed matvec (4 parts over 342 c2) ----
                {
                    int j = tid & 255, part = tid >> 8;
                    const ull* w2  = (const ull*)d_Wct2;
                    const ull* cx2 = (const ull*)cx;
                    ull acc = 0ull;
                    int c20 = part*86;
                    int c21 = c20 + 86; if(c21 > 342) c21 = 342;
#pragma unroll 4
                    for(int c2=c20;c2<c21;c2++)
                        fma2(acc, w2[c2*256 + j], cx2[c2]);
                    float2 v = unpack2(acc);
                    sacc[part][j] = v.x + v.y;
                }
                __syncthreads();
                if(tid < HID){
                    float v = sacc[0][tid] + sacc[1][tid] + sacc[2][tid] + sacc[3][tid]
                            + d_stall[(size_t)(t2*BB+b)*HID + tid];
                    os[tid] = fmaxf(v, d_locw[b*HID + tid]);
                }
                __syncthreads();
                {
                    int j2 = tid & 127, p8 = tid >> 7;    // 8 parts of 32 c
                    float pr = 0.f;
                    if(j2 < VOC){
#pragma unroll 4
                        for(int c=p8*32; c<p8*32+32; c++)
                            pr = fmaf(d_WoutT[c*VOC + j2], os[c], pr);
                    }
                    pp8[p8][j2] = pr;
                }
                __syncthreads();
                if(tid < VOC){
                    float v = bout[tid];
#pragma unroll
                    for(int k=0;k<8;k++) v += pp8[k][tid];
                    out_probs[((size_t)(b*TT + t2))*VOC + tid] = v;
                }
            }
        }

        // ---- single per-b barrier (17 E/P blocks) ----
        if(p < TT){
            __syncthreads();
            bt += 17;
            if(tid==0){
                __threadfence();
                atomicAdd(&d_bcnt[b*32], 1u);
                while(*(volatile unsigned*)&d_bcnt[b*32] < bt) __nanosleep(16);
                __threadfence();
            }
            __syncthreads();
        }
    }
}

// ---------------- launch ----------------
extern "C" void kernel_launch(void* const* d_in, const int* in_sizes, int n_in,
                              void* d_out, int out_size){
    const float* cnn     = (const float*)d_in[0];
    const int*   labels  = (const int*)  d_in[1];
    const float* locp    = (const float*)d_in[2];
    const float* imask   = (const float*)d_in[3];
    const float* W_init  = (const float*)d_in[5];
    const float* b_init  = (const float*)d_in[6];
    const float* emb     = (const float*)d_in[7];
    const float* W_ih    = (const float*)d_in[8];
    const float* b_ih    = (const float*)d_in[9];
    const float* W_hh    = (const float*)d_in[10];
    const float* b_hh    = (const float*)d_in[11];
    const float* W_hq    = (const float*)d_in[12];
    const float* b_hq    = (const float*)d_in[13];
    const float* K_cov   = (const float*)d_in[14];
    const float* W_att   = (const float*)d_in[15];
    const float* W_ac    = (const float*)d_in[16];
    const float* b_ac    = (const float*)d_in[17];
    const float* K_enc   = (const float*)d_in[18];
    const float* b_enc   = (const float*)d_in[19];
    const float* W_state = (const float*)d_in[20];
    const float* b_state = (const float*)d_in[21];
    const float* W_embw  = (const float*)d_in[22];
    const float* b_embw  = (const float*)d_in[23];
    const float* W_ctx   = (const float*)d_in[24];
    const float* b_ctx   = (const float*)d_in[25];
    const float* W_out   = (const float*)d_in[26];
    const float* b_out   = (const float*)d_in[27];
    const float* W_loc   = (const float*)d_in[28];
    const float* b_loc   = (const float*)d_in[29];

    float* out_probs  = (float*)d_out;
    float* out_alphas = (float*)d_out + (size_t)BB*TT*VOC;

    k_preA<<<PA_TOT, 256>>>(imask, K_cov, labels, emb, W_hh, W_hq, W_state, W_out, W_ctx);
    k_preB<<<PB_TOT, 256>>>(cnn, K_enc, b_enc, W_ih, b_ih, W_embw, b_embw, W_att);
    k_preC<<<512, 256>>>(W_init, b_init, W_loc, b_loc, locp);
    k_loop<<<BB*18, 1024>>>(cnn, W_ac, b_ac, b_out, b_hh, b_hq, b_state, b_ctx,
                            out_probs, out_alphas);
}

// round 16
// speedup vs baseline: 1.8647x; 1.8647x over previous
#include <cuda_runtime.h>
#include <math.h>

// ---------------- problem constants ----------------
#define BB   8
#define CC   684
#define HHD  16
#define WWD  64
#define PP   1024
#define TT   32
#define HID  256
#define ATT  512
#define COVD 512
#define VOC  111
#define LOCD 432
#define KC   11
#define RAT  16

typedef unsigned long long ull;

// ---------------- scratch ----------------
__device__ float d_mask[BB*PP];
__device__ float d_msum[BB];
__device__ float d_avg[BB*CC];
__device__ float d_hid0[BB*HID];
__device__ float d_locw[BB*HID];
__device__ float d_kcovT[KC*KC*COVD];
__device__ float d_KfT[(KC*KC+3)*ATT];    // +3 pad rows for prefetch pipeline
__device__ float d_ctrans[(size_t)BB*PP*ATT];
__device__ float d_embseq[TT*BB*HID];
__device__ float d_giall[TT*BB*3*HID];
__device__ float d_embwall[TT*BB*HID];
__device__ float d_queryall[TT*BB*ATT];
__device__ float d_stall[TT*BB*HID];
__device__ float d_asum[2][BB*PP];
__device__ float d_ealpha[2][BB*PP];      // exp(e - Mrow) * mask
__device__ float d_MS[2][BB*32];          // per (b,row): (max, expsum)
__device__ float d_Whh2[HID*3*HID];       // [c/2][row768][2]
__device__ float d_Whq2[HID*ATT];         // [c/2][q512][2]
__device__ float d_Wst2[HID*HID];         // [c/2][j256][2]
__device__ float d_Wct2[(CC/2)*2*HID];    // [c/2][j256][2]
__device__ float d_WoutT[HID*VOC];        // [c][v]
__device__ unsigned d_bcnt[BB*32];        // loop barrier, padded
__device__ unsigned d_qflag[BB*32];       // chain progress flag, padded

// ---------------- helpers ----------------
__device__ __forceinline__ float warp_red(float s){
#pragma unroll
    for(int o=16;o;o>>=1) s += __shfl_down_sync(0xffffffffu, s, o);
    return s;
}
__device__ __forceinline__ ull pack2(float lo, float hi){
    ull r; asm("mov.b64 %0, {%1,%2};" : "=l"(r) : "f"(lo), "f"(hi)); return r;
}
__device__ __forceinline__ void fma2(ull &d, ull a, ull b){
    asm("fma.rn.f32x2 %0, %1, %2, %0;" : "+l"(d) : "l"(a), "l"(b));
}
__device__ __forceinline__ float2 unpack2(ull v){
    float2 f; asm("mov.b64 {%0,%1}, %2;" : "=f"(f.x), "=f"(f.y) : "l"(v)); return f;
}
__device__ __forceinline__ float tanha(float x){
    asm("tanh.approx.f32 %0, %0;" : "+f"(x)); return x;
}

// =================== Launch 0: k_preA ===================
#define PA_KC   8
#define PA_EMB  (PA_KC+242)
#define PA_WHH  (PA_EMB+256)
#define PA_WHQ  (PA_WHH+768)
#define PA_WST  (PA_WHQ+512)
#define PA_WOUT (PA_WST+256)
#define PA_WCT  (PA_WOUT+112)
#define PA_TOT  (PA_WCT+684)

__global__ void __launch_bounds__(256) k_preA(
    const float* __restrict__ imask, const float* __restrict__ K_cov,
    const int*   __restrict__ labels,const float* __restrict__ emb,
    const float* __restrict__ W_hh,  const float* __restrict__ W_hq,
    const float* __restrict__ W_state,const float* __restrict__ W_out,
    const float* __restrict__ W_ctx)
{
    const int blk = blockIdx.x, tid = threadIdx.x;
    __shared__ float red[256];

    if(blk < PA_KC){
        int b = blk;
        float s = 0.f;
        for(int i=tid;i<PP;i+=256){
            int hh = i>>6, ww = i&63;
            float m = imask[(size_t)b*(256*1024) + (size_t)(hh*RAT)*1024 + ww*RAT];
            d_mask[b*PP+i] = m;
            d_asum[0][b*PP+i] = 0.f;
            s += m;
        }
        red[tid]=s; __syncthreads();
        for(int o=128;o;o>>=1){ if(tid<o) red[tid]+=red[tid+o]; __syncthreads(); }
        if(tid==0){ d_msum[b]=red[0]; d_bcnt[b*32]=0u; d_qflag[b*32]=0u; }
    } else if(blk < PA_EMB){
        int e = (blk-PA_KC)*256 + tid;
        if(e < COVD*KC*KC){
            int c = e/(KC*KC), ij = e - c*(KC*KC);
            d_kcovT[ij*COVD + c] = K_cov[e];
        }
    } else if(blk < PA_WHH){
        int e = (blk-PA_EMB)*256 + tid;
        int k = e & (HID-1);
        int tb = e >> 8;
        int b = tb & 7, t = tb >> 3;
        int lbl = (t==0) ? 1 : labels[b*TT + (t-1)];
        d_embseq[e] = emb[(size_t)lbl*HID + k];
    } else if(blk < PA_WHQ){
        int e = (blk-PA_WHH)*256 + tid;   // 768*256
        int r = e >> 8, c = e & 255;
        d_Whh2[(c>>1)*1536 + r*2 + (c&1)] = W_hh[e];
    } else if(blk < PA_WST){
        int e = (blk-PA_WHQ)*256 + tid;   // 512*256
        int q = e >> 8, c = e & 255;
        d_Whq2[(c>>1)*1024 + q*2 + (c&1)] = W_hq[e];
    } else if(blk < PA_WOUT){
        int e = (blk-PA_WST)*256 + tid;   // 256*256
        int j = e >> 8, c = e & 255;
        d_Wst2[(c>>1)*512 + j*2 + (c&1)] = W_state[e];
    } else if(blk < PA_WCT){
        int e = (blk-PA_WOUT)*256 + tid;  // VOC*256
        if(e < VOC*HID){
            int v = e >> 8, c = e & 255;
            d_WoutT[c*VOC + v] = W_out[e];
        }
    } else {
        int e = (blk-PA_WCT)*256 + tid;   // 256*684 = 175104
        if(e < HID*CC){
            int c = e % CC, j = e / CC;
            d_Wct2[(c>>1)*512 + j*2 + (c&1)] = W_ctx[(size_t)j*CC + c];
        }
    }
}

// =================== Launch 1: k_preB (GEMMs) ===================
#define PB_GI  256
#define PB_EW  (PB_GI+48)
#define PB_KF  (PB_EW+16)
#define PB_AVG (PB_KF+16)
#define PB_TOT (PB_AVG+684)

// 128x128 tile reading A directly from cnn (NCHW): px picks (b, 128-p slab).
__device__ void gemm128cnn(const float* __restrict__ cnn,
                           const float* __restrict__ Wt,
                           const float* __restrict__ bias,
                           float* __restrict__ out, int px, int nx,
                           float2 (*As2)[137], float (*Bs)[138])
{
    int p0 = px*128, a0 = nx*128;
    int bb = px >> 3, pp0 = (px & 7) * 128;
    int tid = threadIdx.x;
    int tx = tid & 15, ty = tid >> 4;
    ull acc[8][4];
#pragma unroll
    for(int r=0;r<8;r++)
#pragma unroll
        for(int aa=0;aa<4;aa++) acc[r][aa]=0ull;

    for(int ck=0; ck<CC; ck+=12){
#pragma unroll
        for(int l=0;l<6;l++){
            int lin = tid + l*256;
            int r = lin & 127, k = lin >> 7;
            float av = cnn[((size_t)(bb*CC + ck + k))*PP + pp0 + r];
            As2[k][r] = make_float2(av, av);
        }
#pragma unroll
        for(int l=0;l<6;l++){
            int lin = tid + l*256;
            int k = lin % 12, r = lin / 12;
            Bs[k][r] = Wt[(size_t)(a0+r)*CC + ck + k];
        }
        __syncthreads();
#pragma unroll
        for(int k=0;k<12;k++){
            ull ra[8], rb[4];
#pragma unroll
            for(int r=0;r<8;r++) ra[r] = *(const ull*)&As2[k][ty*8+r];
#pragma unroll
            for(int aa=0;aa<4;aa++) rb[aa] = *(const ull*)&Bs[k][tx*2 + aa*32];
#pragma unroll
            for(int r=0;r<8;r++)
#pragma unroll
                for(int aa=0;aa<4;aa++) fma2(acc[r][aa], ra[r], rb[aa]);
        }
        __syncthreads();
    }
#pragma unroll
    for(int r=0;r<8;r++){
        int p = p0 + ty*8 + r;
#pragma unroll
        for(int aa=0;aa<4;aa++){
            int a = a0 + tx*2 + aa*32;
            float2 v = unpack2(acc[r][aa]);
            out[(size_t)p*ATT + a]   = v.x + bias[a];
            out[(size_t)p*ATT + a+1] = v.y + bias[a+1];
        }
    }
}

__device__ void gemm64(const float* __restrict__ A, int M, int K,
                       const float* __restrict__ Wt, const float* __restrict__ bias,
                       float* __restrict__ out, int N, int ptile, int ntile,
                       float2 (*As)[68], float (*Bs)[68])
{
    int pt = ptile*64, at = ntile*64;
    int tid = threadIdx.x;
    int tx = tid & 15, ty = tid >> 4;
    ull acc2[4][2];
#pragma unroll
    for(int i=0;i<4;i++){ acc2[i][0]=0ull; acc2[i][1]=0ull; }

    for(int c0=0;c0<K;c0+=16){
#pragma unroll
        for(int l=0;l<4;l++){
            int lin = tid + l*256;
            int k = lin & 15, r = lin >> 4;
            int c = c0 + k;
            float av = (c < K && pt+r < M) ? A[((size_t)(pt+r))*K + c] : 0.f;
            As[k][r] = make_float2(av, av);
            Bs[k][r] = (c < K) ? Wt[((size_t)(at+r))*K + c] : 0.f;
        }
        __syncthreads();
#pragma unroll
        for(int k=0;k<16;k++){
            ull ra2[4], rb2[2];
#pragma unroll
            for(int i=0;i<4;i++) ra2[i] = *(const ull*)&As[k][ty*4+i];
            rb2[0] = *(const ull*)&Bs[k][tx*4];
            rb2[1] = *(const ull*)&Bs[k][tx*4+2];
#pragma unroll
            for(int i=0;i<4;i++){
                fma2(acc2[i][0], ra2[i], rb2[0]);
                fma2(acc2[i][1], ra2[i], rb2[1]);
            }
        }
        __syncthreads();
    }
#pragma unroll
    for(int i=0;i<4;i++){
        int p = pt + ty*4 + i;
        if(p < M){
#pragma unroll
            for(int jp=0;jp<2;jp++){
                int aa = at + tx*4 + jp*2;
                float2 v = unpack2(acc2[i][jp]);
                float b0 = bias ? bias[aa]   : 0.f;
                float b1 = bias ? bias[aa+1] : 0.f;
                out[(size_t)p*N + aa]   = v.x + b0;
                out[(size_t)p*N + aa+1] = v.y + b1;
            }
        }
    }
}

__global__ void __launch_bounds__(256,2) k_preB(
    const float* __restrict__ cnn,
    const float* __restrict__ K_enc, const float* __restrict__ b_enc,
    const float* __restrict__ W_ih,  const float* __restrict__ b_ih,
    const float* __restrict__ W_embw,const float* __restrict__ b_embw,
    const float* __restrict__ W_att)
{
    __shared__ float2 As2[12][137];
    __shared__ float  Bsb[12][138];
    __shared__ float2 As[16][68];
    __shared__ float  Bs[16][68];
    const int blk = blockIdx.x;

    if(blk < PB_GI){
        int i = blk;                  // 64 ptiles x 4 ntiles
        gemm128cnn(cnn, K_enc, b_enc, d_ctrans, i & 63, i >> 6, As2, Bsb);
    } else if(blk < PB_EW){
        int i = blk - PB_GI;
        gemm64(d_embseq, TT*BB, HID, W_ih, b_ih, d_giall, 3*HID, i & 3, i >> 2, As, Bs);
    } else if(blk < PB_KF){
        int i = blk - PB_EW;
        gemm64(d_embseq, TT*BB, HID, W_embw, b_embw, d_embwall, HID, i & 3, i >> 2, As, Bs);
    } else if(blk < PB_AVG){
        int i = blk - PB_KF;
        gemm64(d_kcovT, KC*KC, COVD, W_att, (const float*)0, d_KfT, ATT, i & 1, i >> 1, As, Bs);
    } else {
        int gw = (blk - PB_AVG)*8 + (threadIdx.x >> 5);
        int lane = threadIdx.x & 31;
        if(gw < BB*CC){
            int b = gw / CC;
            const float* x = cnn + (size_t)gw*PP;
            const float* m = d_mask + b*PP;
            float s = 0.f;
            for(int p=lane;p<PP;p+=32) s += x[p]*m[p];
            s = warp_red(s);
            if(lane==0) d_avg[gw] = s / d_msum[b];
        }
    }
}

// =================== Launch 2: k_preC ===================
__global__ void __launch_bounds__(256) k_preC(
    const float* __restrict__ W_init, const float* __restrict__ b_init,
    const float* __restrict__ W_loc,  const float* __restrict__ b_loc,
    const float* __restrict__ locp)
{
    int gw = blockIdx.x*8 + (threadIdx.x >> 5);
    int lane = threadIdx.x & 31;
    if(gw < BB*HID){
        int b = gw / HID, j = gw - b*HID;
        const float* wv = W_init + (size_t)j*CC;
        const float* av = d_avg + b*CC;
        float s = 0.f;
        for(int c=lane;c<CC;c+=32) s += wv[c]*av[c];
        s = warp_red(s);
        if(lane==0) d_hid0[gw] = tanhf(s + b_init[j]);
    } else if(gw < 2*BB*HID){
        int g2 = gw - BB*HID;
        int b = g2 / HID, j = g2 - b*HID;
        const float* wv = W_loc + (size_t)j*LOCD;
        const float* xv = locp + (size_t)b*LOCD;
        float s = 0.f;
        for(int c=lane;c<LOCD;c+=32) s += wv[c]*xv[c];
        s = warp_red(s);
        if(lane==0) d_locw[g2] = s + b_loc[j];
    }
}

// =================== Launch 3: k_loop (persistent; chain fused as producer) ===================
__global__ void __launch_bounds__(512,1) k_loop(
    const float* __restrict__ cnn,
    const float* __restrict__ Wac,   const float* __restrict__ bac,
    const float* __restrict__ bout,
    const float* __restrict__ bhh,   const float* __restrict__ bhq,
    const float* __restrict__ bstate,const float* __restrict__ bctx,
    float* __restrict__ out_probs,   float* __restrict__ out_alphas)
{
    const int bid = blockIdx.x;       // 0..143
    const int b = bid / 18;
    const int h = bid - b*18;         // 0..15 E rows; 16 = P block; 17 = chain producer
    const int tid = threadIdx.x;
    const int lane = tid & 31, wid = tid >> 5;
    unsigned bt = 0;

    __shared__ float2 taps2[KC*74];
    __shared__ float  spart[4][4][16];
    __shared__ float  wred[4];
    __shared__ float  rs_s[16];
    __shared__ int    wcnt[16];
    __shared__ int    pl[64];
    __shared__ float  wl[64];
    __shared__ int    nact_s;
    __shared__ float  sacc[2][HID];
    __shared__ float  os[HID];
    __shared__ float  pp4[4][128];
    __shared__ __align__(8) float hc[HID];
    __shared__ __align__(8) float gv[3*HID];   // chain gates; reused as cx[684] in P

    const float bac0 = bac[0];

    // ================= chain producer block =================
    if(h == 17){
        if(tid < HID) hc[tid] = d_hid0[b*HID + tid];
        __syncthreads();
        for(int t=0; t<TT; t++){
            const ull* h2 = (const ull*)hc;
            {
                int r0 = tid;
                int r1 = 512 + (tid & 255);
                bool two = (tid < 256);
                ull a0=0ull, a1=0ull;
                const ull* wp = (const ull*)d_Whh2;
#pragma unroll 16
                for(int c2=0;c2<128;c2++){
                    ull hcv = h2[c2];
                    fma2(a0, wp[c2*768 + r0], hcv);
                    if(two) fma2(a1, wp[c2*768 + r1], hcv);
                }
                float2 v0 = unpack2(a0); gv[r0] = v0.x + v0.y;
                if(two){ float2 v1 = unpack2(a1); gv[r1] = v1.x + v1.y; }
            }
            __syncthreads();
            if(tid < HID){
                int j = tid;
                float hr = bhh[j]       + gv[j];
                float hz = bhh[HID+j]   + gv[HID+j];
                float hv = bhh[2*HID+j] + gv[2*HID+j];
                const float* gi = d_giall + (size_t)(t*BB+b)*3*HID;
                float r = 1.f/(1.f+expf(-(gi[j]+hr)));
                float z = 1.f/(1.f+expf(-(gi[HID+j]+hz)));
                float n = tanhf(gi[2*HID+j] + r*hv);
                gv[j] = (1.f - z)*n + z*hc[j];
            }
            __syncthreads();
            if(tid < HID) hc[tid] = gv[tid];
            __syncthreads();
            const ull* hn2 = (const ull*)hc;
            {
                int q = tid;
                int j = tid & 255;
                bool st = (tid < 256);
                ull aq = 0ull, as2 = 0ull;
                const ull* wq = (const ull*)d_Whq2;
                const ull* ws = (const ull*)d_Wst2;
#pragma unroll 16
                for(int c2=0;c2<128;c2++){
                    ull hcv = hn2[c2];
                    fma2(aq, wq[c2*512 + q], hcv);
                    if(st) fma2(as2, ws[c2*256 + j], hcv);
                }
                float2 vq = unpack2(aq);
                d_queryall[(size_t)(t*BB+b)*ATT + q] = bhq[q] + vq.x + vq.y;
                if(st){
                    float2 vs = unpack2(as2);
                    d_stall[(size_t)(t*BB+b)*HID + j] = bstate[j] + bctx[j]
                        + d_embwall[(size_t)(t*BB+b)*HID + j] + vs.x + vs.y;
                }
            }
            __threadfence();
            __syncthreads();
            if(tid==0) *((volatile unsigned*)&d_qflag[b*32]) = (unsigned)(t+1);
        }
        return;
    }

    // ================= E / P blocks =================
    for(int p=0; p<=TT; p++){
        float M = -3.4e38f, S1e = 1e-10f;
        const float* ms = d_MS[(p-1)&1] + b*32;
        if(p > 0){
            float s = 0.f;
#pragma unroll
            for(int r=0;r<16;r++) M = fmaxf(M, ms[2*r]);
#pragma unroll
            for(int r=0;r<16;r++) s += expf(ms[2*r]-M)*ms[2*r+1];
            S1e = s + 1e-10f;
        }

        if(h < 16){
            if(p > 0){
                if(tid < 16) rs_s[tid] = expf(ms[2*tid]-M)/S1e;
                __syncthreads();
                if(tid < 64){
                    int px = b*PP + h*WWD + tid;
                    float a = d_ealpha[(p-1)&1][px] * rs_s[h];
                    out_alphas[((size_t)(b*TT + (p-1)))*PP + h*WWD + tid] = a;
                    d_asum[p&1][px] = d_asum[(p-1)&1][px] + a;
                }
                if(p < TT){
                    for(int idx=tid; idx<KC*74; idx+=512){
                        int i = idx/74, w2 = idx - i*74;
                        int r = h + i - 5, wg = w2 - 5;
                        float v = 0.f;
                        if(r>=0 && r<HHD && wg>=0 && wg<WWD){
                            int px = b*PP + r*WWD + wg;
                            v = d_asum[(p-1)&1][px] + d_ealpha[(p-1)&1][px]*rs_s[r];
                        }
                        taps2[idx] = make_float2(v, v);
                    }
                    // merged: taps visibility + query(p) availability
                    if(tid==0){
                        while(*((volatile unsigned*)&d_qflag[b*32]) < (unsigned)(p+1))
                            __nanosleep(32);
                    }
                    __syncthreads();
                }
            }

            if(p < TT){
                const int ag = tid & 127, wg = tid >> 7;
                const int a0 = ag << 2,  w0 = wg << 4;

                if(p == 0){
                    if(tid==0){
                        while(*((volatile unsigned*)&d_qflag[b*32]) < (unsigned)(p+1))
                            __nanosleep(32);
                    }
                    __syncthreads();
                }

                float4 q4  = *(const float4*)(d_queryall + (size_t)(p*BB+b)*ATT + a0);
                float4 wa4 = *(const float4*)(Wac + a0);
                const float* ctbase = d_ctrans + ((size_t)(b*PP + h*WWD + w0))*ATT + a0;
                int wiw = (tid >> 5) & 3;

#pragma unroll
                for(int half=0; half<2; half++){
                    ull a01[8], a23[8];
#pragma unroll
                    for(int w=0;w<8;w++){ a01[w]=0ull; a23[w]=0ull; }

                    if(p > 0){
                        // rolling depth-3 kf prefetch; static taps offsets
                        const float* kfp = d_KfT + a0;
                        float4 pre0 = *(const float4*)(kfp);
                        float4 pre1 = *(const float4*)(kfp + ATT);
                        float4 pre2 = *(const float4*)(kfp + 2*ATT);
                        const float* kfn = kfp + (size_t)3*ATT;
#pragma unroll 1
                        for(int i=0;i<KC;i++){
                            const ull* trow = (const ull*)(&taps2[i*74 + w0 + half*8]);
#pragma unroll
                            for(int j=0;j<KC;j++){
                                ull k01 = pack2(pre0.x, pre0.y);
                                ull k23 = pack2(pre0.z, pre0.w);
                                pre0 = pre1; pre1 = pre2;
                                pre2 = *(const float4*)kfn;   // pad rows keep this in-bounds
                                kfn += ATT;
#pragma unroll
                                for(int w=0;w<8;w++){
                                    ull tp = trow[j+w];
                                    fma2(a01[w], k01, tp);
                                    fma2(a23[w], k23, tp);
                                }
                            }
                        }
                    }

                    // epilogue for this half
#pragma unroll
                    for(int w=0;w<8;w++){
                        float4 ct = *(const float4*)(ctbase + (size_t)(half*8+w)*ATT);
                        float2 v01 = unpack2(a01[w]);
                        float2 v23 = unpack2(a23[w]);
                        float v = wa4.x * tanha(q4.x + v01.x + ct.x)
                                + wa4.y * tanha(q4.y + v01.y + ct.y)
                                + wa4.z * tanha(q4.z + v23.x + ct.z)
                                + wa4.w * tanha(q4.w + v23.y + ct.w);
#pragma unroll
                        for(int o=16;o;o>>=1) v += __shfl_down_sync(0xffffffffu, v, o);
                        if(lane==0) spart[wg][wiw][half*8+w] = v;
                    }
                }
                __syncthreads();
                float ev = 0.f;
                if(tid < 64){
                    int wgo = tid >> 4, wlx = tid & 15;
                    ev = spart[wgo][0][wlx] + spart[wgo][1][wlx]
                       + spart[wgo][2][wlx] + spart[wgo][3][wlx] + bac0;
                    float m = ev;
#pragma unroll
                    for(int o=16;o;o>>=1) m = fmaxf(m, __shfl_xor_sync(0xffffffffu, m, o));
                    if(lane==0) wred[wid] = m;
                }
                __syncthreads();
                float Mr = fmaxf(wred[0], wred[1]);
                if(tid < 64){
                    int px = b*PP + h*WWD + tid;
                    float s = expf(ev - Mr)*d_mask[px];
                    d_ealpha[p&1][px] = s;
#pragma unroll
                    for(int o=16;o;o>>=1) s += __shfl_xor_sync(0xffffffffu, s, o);
                    if(lane==0) wred[2+wid] = s;
                }
                __syncthreads();
                if(tid==0){
                    float* msd = d_MS[p&1] + b*32 + h*2;
                    msd[0] = Mr; msd[1] = wred[2] + wred[3];
                }
            }
        } else {
            // ================= P block: ctx + probs for t' = p-1 =================
            if(p > 0){
                int t2 = p-1;
                if(tid < 16) rs_s[tid] = expf(ms[2*tid]-M)/S1e;
                if(tid==0){
                    while(*((volatile unsigned*)&d_qflag[b*32]) < (unsigned)p)
                        __nanosleep(32);
                }
                __syncthreads();

                int p0 = tid, p1 = tid + 512;
                float a0 = d_ealpha[(p-1)&1][b*PP + p0] * rs_s[tid>>6];
                float a1 = d_ealpha[(p-1)&1][b*PP + p1] * rs_s[(tid>>6)+8];

                bool act0 = a0 > 0.02f, act1 = a1 > 0.02f;
                unsigned m0 = __ballot_sync(0xffffffffu, act0);
                unsigned m1 = __ballot_sync(0xffffffffu, act1);
                if(lane==0) wcnt[wid] = __popc(m0) + __popc(m1);
                __syncthreads();
                if(tid < 16){
                    int v = wcnt[tid], sc = v;
#pragma unroll
                    for(int o=1;o<16;o<<=1){ int u=__shfl_up_sync(0x0000ffffu, sc, o); if(tid>=o) sc += u; }
                    wcnt[tid] = sc - v;
                    if(tid==15) nact_s = sc;
                }
                __syncthreads();
                int base = wcnt[wid];
                unsigned lm = (1u<<lane) - 1u;
                if(act0){ int idx = base + __popc(m0 & lm); if(idx<64){ pl[idx]=p0; wl[idx]=a0; } }
                if(act1){ int idx = base + __popc(m0) + __popc(m1 & lm); if(idx<64){ pl[idx]=p1; wl[idx]=a1; } }
                __syncthreads();

                // ---- C-space ctx gather from cnn directly (reuse gv as cx) ----
                float* cx = gv;
                {
                    int n = nact_s < 64 ? nact_s : 64;
                    for(int c = tid; c < CC; c += 512){
                        const float* cp = cnn + ((size_t)(b*CC + c))*PP;
                        float s = 0.f;
                        for(int i=0;i<n;i++)
                            s = fmaf(wl[i], cp[pl[i]], s);
                        cx[c] = s;
                    }
                }
                __syncthreads();
                // ---- ctx @ W_ctx^T via packed matvec ----
                {
                    int j = tid & 255, part = tid >> 8;
                    const ull* w2  = (const ull*)d_Wct2;
                    const ull* cx2 = (const ull*)cx;
                    ull acc = 0ull;
                    int c20 = part*171, c21 = c20 + 171;
#pragma unroll 4
                    for(int c2=c20;c2<c21;c2++)
                        fma2(acc, w2[c2*256 + j], cx2[c2]);
                    float2 v = unpack2(acc);
                    sacc[part][j] = v.x + v.y;
                }
                __syncthreads();
                if(tid < HID){
                    float v = sacc[0][tid] + sacc[1][tid]
                            + d_stall[(size_t)(t2*BB+b)*HID + tid];
                    os[tid] = fmaxf(v, d_locw[b*HID + tid]);
                }
                __syncthreads();
                {
                    int j2 = tid & 127, p4 = tid >> 7;
                    float pr = 0.f;
                    if(j2 < VOC){
#pragma unroll 4
                        for(int c=p4*64; c<p4*64+64; c++)
                            pr = fmaf(d_WoutT[c*VOC + j2], os[c], pr);
                    }
                    pp4[p4][j2] = pr;
                }
                __syncthreads();
                if(tid < VOC){
                    out_probs[((size_t)(b*TT + t2))*VOC + tid] =
                        bout[tid] + pp4[0][tid] + pp4[1][tid] + pp4[2][tid] + pp4[3][tid];
                }
            }
        }

        // ---- single per-b barrier (17 E/P blocks) ----
        if(p < TT){
            __syncthreads();
            bt += 17;
            if(tid==0){
                __threadfence();
                atomicAdd(&d_bcnt[b*32], 1u);
                while(*(volatile unsigned*)&d_bcnt[b*32] < bt) __nanosleep(16);
                __threadfence();
            }
            __syncthreads();
        }
    }
}

// ---------------- launch ----------------
extern "C" void kernel_launch(void* const* d_in, const int* in_sizes, int n_in,
                              void* d_out, int out_size){
    const float* cnn     = (const float*)d_in[0];
    const int*   labels  = (const int*)  d_in[1];
    const float* locp    = (const float*)d_in[2];
    const float* imask   = (const float*)d_in[3];
    const float* W_init  = (const float*)d_in[5];
    const float* b_init  = (const float*)d_in[6];
    const float* emb     = (const float*)d_in[7];
    const float* W_ih    = (const float*)d_in[8];
    const float* b_ih    = (const float*)d_in[9];
    const float* W_hh    = (const float*)d_in[10];
    const float* b_hh    = (const float*)d_in[11];
    const float* W_hq    = (const float*)d_in[12];
    const float* b_hq    = (const float*)d_in[13];
    const float* K_cov   = (const float*)d_in[14];
    const float* W_att   = (const float*)d_in[15];
    const float* W_ac    = (const float*)d_in[16];
    const float* b_ac    = (const float*)d_in[17];
    const float* K_enc   = (const float*)d_in[18];
    const float* b_enc   = (const float*)d_in[19];
    const float* W_state = (const float*)d_in[20];
    const float* b_state = (const float*)d_in[21];
    const float* W_embw  = (const float*)d_in[22];
    const float* b_embw  = (const float*)d_in[23];
    const float* W_ctx   = (const float*)d_in[24];
    const float* b_ctx   = (const float*)d_in[25];
    const float* W_out   = (const float*)d_in[26];
    const float* b_out   = (const float*)d_in[27];
    const float* W_loc   = (const float*)d_in[28];
    const float* b_loc   = (const float*)d_in[29];

    float* out_probs  = (float*)d_out;
    float* out_alphas = (float*)d_out + (size_t)BB*TT*VOC;

    k_preA<<<PA_TOT, 256>>>(imask, K_cov, labels, emb, W_hh, W_hq, W_state, W_out, W_ctx);
    k_preB<<<PB_TOT, 256>>>(cnn, K_enc, b_enc, W_ih, b_ih, W_embw, b_embw, W_att);
    k_preC<<<512, 256>>>(W_init, b_init, W_loc, b_loc, locp);
    k_loop<<<BB*18, 512>>>(cnn, W_ac, b_ac, b_out, b_hh, b_hq, b_state, b_ctx,
                           out_probs, out_alphas);
}